// round 16
// baseline (speedup 1.0000x reference)
#include <cuda_runtime.h>
#include <cuda_bf16.h>
#include <cstdint>

#define N_NODES 40000
#define N_EDGES 320000
#define C 256
#define KORD 5

#define NKTILE 40          // 5 segs x 8 k32-tiles
#define ACOLS 2560         // per-row bf16 cols: 5 segs x (256 hi + 256 lo)

// ---------------- scratch (device globals; no allocation allowed) ----------------
__device__ int   g_is64;
__device__ int   g_cnt[N_NODES];
__device__ int   g_fill[N_NODES];
__device__ int   g_rowptr[N_NODES + 1];
__device__ float g_dis[N_NODES];
__device__ int   g_col[N_EDGES];
__device__ float g_val[N_EDGES];
__device__ float g_T1[(size_t)N_NODES * C];
__device__ float g_T2[(size_t)N_NODES * C];
__device__ float g_T3[(size_t)N_NODES * C];
__device__ float g_T4[(size_t)N_NODES * C];
__device__ __align__(16) __nv_bfloat16 g_Abf[(size_t)N_NODES * ACOLS];      // ~205 MB
__device__ __align__(16) __nv_bfloat16 g_Bw[(size_t)NKTILE * 2 * 32 * 256]; // hi/lo weight tiles

__device__ __forceinline__ float* selT(int i) {
    switch (i) {
        case 1: return g_T1;
        case 2: return g_T2;
        case 3: return g_T3;
        default: return g_T4;
    }
}
__device__ __forceinline__ int edge_idx(const int* __restrict__ ei32, int which, int e) {
    if (g_is64) {
        const long long* p = (const long long*)ei32;
        return (int)p[(size_t)which * N_EDGES + e];
    }
    return ei32[which * N_EDGES + e];
}
__device__ __forceinline__ uint32_t smem_u32(const void* p) {
    uint32_t a;
    asm("{ .reg .u64 t; cvta.to.shared.u64 t, %1; cvt.u32.u64 %0, t; }" : "=r"(a) : "l"(p));
    return a;
}

// ---------------- setup kernels ----------------
__global__ void init_kernel(const int* __restrict__ ei32) {
    int i = blockIdx.x * blockDim.x + threadIdx.x;
    if (i < N_NODES) { g_cnt[i] = 0; g_fill[i] = 0; }
    if (blockIdx.x == 0 && threadIdx.x == 0) {
        int is64 = 1;
        for (int k = 0; k < 64; k++)
            if (ei32[2 * k + 1] != 0) { is64 = 0; break; }
        g_is64 = is64;
    }
}
__global__ void count_kernel(const int* __restrict__ ei32) {
    int e = blockIdx.x * blockDim.x + threadIdx.x;
    if (e < N_EDGES) {
        int r = edge_idx(ei32, 0, e);
        int c = edge_idx(ei32, 1, e);
        if (r != c && r >= 0 && r < N_NODES) atomicAdd(&g_cnt[r], 1);
    }
}

// single-block scan: 1024 threads x 40 items, warp-shuffle block scan + fused deg_inv_sqrt
#define SCAN_IPT 40
__global__ __launch_bounds__(1024, 1)
void scan_kernel() {
    __shared__ int wsum[32];
    int tid = threadIdx.x;
    int lane = tid & 31, wid = tid >> 5;
    int base = tid * SCAN_IPT;

    int vals[SCAN_IPT];
    int sum = 0;
#pragma unroll
    for (int i = 0; i < SCAN_IPT; i++) {
        int idx = base + i;
        int v = (idx < N_NODES) ? g_cnt[idx] : 0;
        sum += v;
        vals[i] = sum;
    }
    int s = sum;
#pragma unroll
    for (int off = 1; off < 32; off <<= 1) {
        int t = __shfl_up_sync(0xFFFFFFFFu, s, off);
        if (lane >= off) s += t;
    }
    if (lane == 31) wsum[wid] = s;
    __syncthreads();
    if (wid == 0) {
        int w = wsum[lane];
#pragma unroll
        for (int off = 1; off < 32; off <<= 1) {
            int t = __shfl_up_sync(0xFFFFFFFFu, w, off);
            if (lane >= off) w += t;
        }
        wsum[lane] = w;
    }
    __syncthreads();
    int prefix = s - sum + (wid > 0 ? wsum[wid - 1] : 0);

    if (tid == 0) g_rowptr[0] = 0;
#pragma unroll
    for (int i = 0; i < SCAN_IPT; i++) {
        int idx = base + i;
        if (idx < N_NODES) {
            g_rowptr[idx + 1] = prefix + vals[i];
            int d = (i == 0) ? vals[0] : (vals[i] - vals[i - 1]);
            g_dis[idx] = (d > 0) ? rsqrtf((float)d) : 0.0f;
        }
    }
}

__global__ void scatter_kernel(const int* __restrict__ ei32,
                               const float* __restrict__ ew) {
    int e = blockIdx.x * blockDim.x + threadIdx.x;
    if (e < N_EDGES) {
        int r = edge_idx(ei32, 0, e);
        int c = edge_idx(ei32, 1, e);
        if (r != c && r >= 0 && r < N_NODES && c >= 0 && c < N_NODES) {
            float lap = -g_dis[r] * ew[e] * g_dis[c];
            int pos = g_rowptr[r] + atomicAdd(&g_fill[r], 1);
            g_col[pos] = c;
            g_val[pos] = lap;
        }
    }
}

// pack 4 floats -> hi/lo bf16 uint2 stores
__device__ __forceinline__ void store_hilo4(__nv_bfloat16* dst, float4 r) {
    __nv_bfloat16 h0 = __float2bfloat16(r.x), h1 = __float2bfloat16(r.y);
    __nv_bfloat16 h2 = __float2bfloat16(r.z), h3 = __float2bfloat16(r.w);
    __nv_bfloat16 l0 = __float2bfloat16(r.x - __bfloat162float(h0));
    __nv_bfloat16 l1 = __float2bfloat16(r.y - __bfloat162float(h1));
    __nv_bfloat16 l2 = __float2bfloat16(r.z - __bfloat162float(h2));
    __nv_bfloat16 l3 = __float2bfloat16(r.w - __bfloat162float(h3));
    __nv_bfloat162 hp0 = {h0, h1}, hp1 = {h2, h3}, lp0 = {l0, l1}, lp1 = {l2, l3};
    uint2 hv = make_uint2(*(uint32_t*)&hp0, *(uint32_t*)&hp1);
    uint2 lv = make_uint2(*(uint32_t*)&lp0, *(uint32_t*)&lp1);
    *(uint2*)dst = hv;
    *(uint2*)(dst + 256) = lv;
}

// seg-0 conversion: x -> bf16 hi/lo, float4 per thread, 4 rows/block
__global__ void xconv_kernel(const float* __restrict__ x) {
    int tid = threadIdx.x;
    int row = blockIdx.x * 4 + (tid >> 6);
    int c4 = (tid & 63) * 4;
    float4 v = *(const float4*)(x + (size_t)row * C + c4);
    store_hilo4(g_Abf + (size_t)row * ACOLS + c4, v);
}

// weight prep: g_Bw[ktile][ph][j][n], ph0=hi, ph1=lo
__global__ void bprep_kernel(const float* __restrict__ w) {
    int blk = blockIdx.x;                 // 0..79
    int ktile = blk >> 1, ph = blk & 1;
    int seg = ktile >> 3, kk = (ktile & 7) << 5;
    int n = threadIdx.x;
    const float* Wseg = w + (size_t)seg * C * C;
    __nv_bfloat16* dst = g_Bw + ((size_t)ktile * 2 + ph) * 32 * 256;
    for (int j = 0; j < 32; j++) {
        float wv = Wseg[(size_t)(kk + j) * C + n];
        __nv_bfloat16 hv = __float2bfloat16(wv);
        dst[j * 256 + n] = ph ? __float2bfloat16(wv - __bfloat162float(hv)) : hv;
    }
}

// ---------------- CSR SpMM (+ fused bf16 hi/lo conversion) ----------------
// 4 rows per block, 64 threads/row, float4 per thread, 2-edge unroll (R11-proven).
__global__ void spmm_kernel(const float* __restrict__ x,
                            int vsel, int ssel, int dsel,
                            float alpha, float beta, int store_f32) {
    const float* v   = (vsel == 0) ? x : selT(vsel);
    const float* sub = (ssel < 0) ? nullptr : ((ssel == 0) ? x : selT(ssel));
    float* out = selT(dsel);

    int tid = threadIdx.x;
    int row = blockIdx.x * 4 + (tid >> 6);
    int c4 = (tid & 63) * 4;

    int s = g_rowptr[row], e = g_rowptr[row + 1];
    float4 a0 = make_float4(0.f, 0.f, 0.f, 0.f);
    float4 a1 = make_float4(0.f, 0.f, 0.f, 0.f);
    int j = s;
    for (; j + 2 <= e; j += 2) {
        int  c0 = g_col[j],   c1 = g_col[j + 1];
        float w0 = g_val[j],  w1 = g_val[j + 1];
        float4 v0 = *(const float4*)(v + (size_t)c0 * C + c4);
        float4 v1 = *(const float4*)(v + (size_t)c1 * C + c4);
        a0.x += w0 * v0.x; a0.y += w0 * v0.y; a0.z += w0 * v0.z; a0.w += w0 * v0.w;
        a1.x += w1 * v1.x; a1.y += w1 * v1.y; a1.z += w1 * v1.z; a1.w += w1 * v1.w;
    }
    if (j < e) {
        int c0 = g_col[j];
        float w0 = g_val[j];
        float4 v0 = *(const float4*)(v + (size_t)c0 * C + c4);
        a0.x += w0 * v0.x; a0.y += w0 * v0.y; a0.z += w0 * v0.z; a0.w += w0 * v0.w;
    }
    float4 r;
    r.x = alpha * (a0.x + a1.x);
    r.y = alpha * (a0.y + a1.y);
    r.z = alpha * (a0.z + a1.z);
    r.w = alpha * (a0.w + a1.w);
    if (sub) {
        float4 sv = *(const float4*)(sub + (size_t)row * C + c4);
        r.x += beta * sv.x; r.y += beta * sv.y; r.z += beta * sv.z; r.w += beta * sv.w;
    }
    if (store_f32) *(float4*)(out + (size_t)row * C + c4) = r;
    store_hilo4(g_Abf + (size_t)row * ACOLS + dsel * 512 + c4, r);
}

// ---------------- bf16 mma.sync GEMM, 3-stage cp.async, 2 CTAs/SM ----------------
// CTA tile 128x128, 256 threads (8 warps: 4M x 2N), grid (2, 313).
// Inner loop: B fragments double-buffered across np so every LDSM has ~12 MMAs
// of slack before its first consumer (hides ~29cyc LDSM latency).
#define MMA(c, a, b) \
    asm volatile("mma.sync.aligned.m16n8k16.row.col.f32.bf16.bf16.f32 " \
        "{%0,%1,%2,%3}, {%4,%5,%6,%7}, {%8,%9}, {%0,%1,%2,%3};" \
        : "+f"((c)[0]), "+f"((c)[1]), "+f"((c)[2]), "+f"((c)[3]) \
        : "r"((a)[0]), "r"((a)[1]), "r"((a)[2]), "r"((a)[3]), "r"((b)[0]), "r"((b)[1]))

#define LDM_X4(r, a) \
    asm volatile("ldmatrix.sync.aligned.m8n8.x4.shared.b16 {%0,%1,%2,%3}, [%4];" \
        : "=r"((r)[0]), "=r"((r)[1]), "=r"((r)[2]), "=r"((r)[3]) : "r"(a))

#define LDM_X4T(r, a) \
    asm volatile("ldmatrix.sync.aligned.m8n8.x4.trans.shared.b16 {%0,%1,%2,%3}, [%4];" \
        : "=r"((r)[0]), "=r"((r)[1]), "=r"((r)[2]), "=r"((r)[3]) : "r"(a))

#define CP16(d, s, n) \
    asm volatile("cp.async.cg.shared.global [%0], [%1], 16, %2;" \
        :: "r"(d), "l"(s), "r"(n) : "memory")
#define CP_COMMIT() asm volatile("cp.async.commit_group;" ::: "memory")
#define CP_WAIT(n)  asm volatile("cp.async.wait_group %0;" :: "n"(n) : "memory")

// stage: Ahi 8KB @0, Alo 8KB @8192, Whi 8KB @16384, Wlo 8KB @24576
#define STG_BYTES 32768
#define NSTAGE 3
#define SM_GEMM (NSTAGE * STG_BYTES)

__global__ __launch_bounds__(256, 2)
void gemm_mma(const float* __restrict__ bias, float* __restrict__ out) {
    extern __shared__ char smem[];
    uint32_t sb = smem_u32(smem);

    int tid = threadIdx.x;
    int lane = tid & 31;
    int wid = tid >> 5;
    int wm = wid & 3, wn = wid >> 2;     // 4 M-warps x 2 N-warps
    int m0 = blockIdx.y * 128;
    int n0 = blockIdx.x * 128;

    // A staging: 512 granules/half (128 rows x 4 chunks of 16B), 2 per thread per half
    int aG0 = tid * 2, aG1 = tid * 2 + 1;
    int aR0 = aG0 >> 2, aC0 = aG0 & 3;
    int aR1 = aG1 >> 2, aC1 = aG1 & 3;
    uint32_t aSz0 = (m0 + aR0 < N_NODES) ? 16u : 0u;
    uint32_t aSz1 = (m0 + aR1 < N_NODES) ? 16u : 0u;
    uint32_t aDst0 = aR0 * 64 + ((aC0 ^ ((aR0 >> 1) & 3)) << 4);
    uint32_t aDst1 = aR1 * 64 + ((aC1 ^ ((aR1 >> 1) & 3)) << 4);
    // B staging: 512 granules/half (32 rows x 16 chunks), 2 per thread per half
    int bG0 = tid * 2, bG1 = tid * 2 + 1;
    int bR0 = bG0 >> 4, bC0 = bG0 & 15;
    int bR1 = bG1 >> 4, bC1 = bG1 & 15;
    uint32_t bDst0 = bR0 * 256 + ((bC0 ^ (bR0 & 7)) << 4);
    uint32_t bDst1 = bR1 * 256 + ((bC1 ^ (bR1 & 7)) << 4);

    // ldmatrix offsets — A rows 64B (4 chunks), B rows 256B (16 chunks)
    uint32_t aOff[2][2];
#pragma unroll
    for (int mt = 0; mt < 2; mt++)
#pragma unroll
        for (int ks = 0; ks < 2; ks++) {
            int row = wm * 32 + mt * 16 + (lane & 15);
            int ch = ks * 2 + (lane >> 4);
            aOff[mt][ks] = row * 64 + ((ch ^ ((row >> 1) & 3)) << 4);
        }
    uint32_t bOff[4][2];
#pragma unroll
    for (int np = 0; np < 4; np++)
#pragma unroll
        for (int ks = 0; ks < 2; ks++) {
            int row = ks * 16 + ((lane >> 3) & 1) * 8 + (lane & 7);
            int ch = wn * 8 + np * 2 + (lane >> 4);
            bOff[np][ks] = row * 256 + ((ch ^ (row & 7)) << 4);
        }

    float acc[2][8][4];
#pragma unroll
    for (int i = 0; i < 2; i++)
#pragma unroll
        for (int j = 0; j < 8; j++)
#pragma unroll
            for (int q = 0; q < 4; q++) acc[i][j][q] = 0.f;

    auto issue = [&](int ktile, int stg) {
        uint32_t base = sb + stg * STG_BYTES;
        int seg = ktile >> 3, kk = (ktile & 7) << 5;
        const __nv_bfloat16* a0 =
            g_Abf + (size_t)(m0 + aR0) * ACOLS + seg * 512 + kk + aC0 * 8;
        const __nv_bfloat16* a1 =
            g_Abf + (size_t)(m0 + aR1) * ACOLS + seg * 512 + kk + aC1 * 8;
        CP16(base + aDst0, a0, aSz0);                 // Ahi
        CP16(base + aDst1, a1, aSz1);
        CP16(base + 8192 + aDst0, a0 + 256, aSz0);    // Alo
        CP16(base + 8192 + aDst1, a1 + 256, aSz1);
        const __nv_bfloat16* bh = g_Bw + (size_t)ktile * 2 * 32 * 256 + n0;
        const __nv_bfloat16* bl = bh + 32 * 256;
        CP16(base + 16384 + bDst0, bh + bR0 * 256 + bC0 * 8, 16u);  // Whi
        CP16(base + 16384 + bDst1, bh + bR1 * 256 + bC1 * 8, 16u);
        CP16(base + 24576 + bDst0, bl + bR0 * 256 + bC0 * 8, 16u);  // Wlo
        CP16(base + 24576 + bDst1, bl + bR1 * 256 + bC1 * 8, 16u);
    };

    issue(0, 0); CP_COMMIT();
    issue(1, 1); CP_COMMIT();

    int stg = 0;
    for (int kt = 0; kt < NKTILE; kt++) {
        if (kt < NKTILE - 1) { CP_WAIT(1); } else { CP_WAIT(0); }
        __syncthreads();
        if (kt + 2 < NKTILE) {
            int ns = stg + 2; if (ns >= NSTAGE) ns -= NSTAGE;
            issue(kt + 2, ns);
            CP_COMMIT();
        }

        uint32_t S = sb + stg * STG_BYTES;
        uint32_t Ahi = S, Alo = S + 8192, Whi = S + 16384, Wlo = S + 24576;
#pragma unroll
        for (int ks = 0; ks < 2; ks++) {
            uint32_t ah[2][4], al[2][4];
            LDM_X4(ah[0], Ahi + aOff[0][ks]);
            LDM_X4(ah[1], Ahi + aOff[1][ks]);
            LDM_X4(al[0], Alo + aOff[0][ks]);
            LDM_X4(al[1], Alo + aOff[1][ks]);

            // B double-buffered across np: LDSMs issued ~12 MMAs ahead of use
            uint32_t bhb[2][4], blb[2][4];
            LDM_X4T(bhb[0], Whi + bOff[0][ks]);
            LDM_X4T(blb[0], Wlo + bOff[0][ks]);
#pragma unroll
            for (int np = 0; np < 4; np++) {
                int cur = np & 1;
                if (np < 3) {
                    LDM_X4T(bhb[cur ^ 1], Whi + bOff[np + 1][ks]);
                    LDM_X4T(blb[cur ^ 1], Wlo + bOff[np + 1][ks]);
                }
                uint32_t* bh = bhb[cur];
                uint32_t* bl = blb[cur];
                MMA(acc[0][np * 2 + 0], ah[0], bh);
                MMA(acc[0][np * 2 + 1], ah[0], bh + 2);
                MMA(acc[1][np * 2 + 0], ah[1], bh);
                MMA(acc[1][np * 2 + 1], ah[1], bh + 2);
                MMA(acc[0][np * 2 + 0], al[0], bh);
                MMA(acc[0][np * 2 + 1], al[0], bh + 2);
                MMA(acc[1][np * 2 + 0], al[1], bh);
                MMA(acc[1][np * 2 + 1], al[1], bh + 2);
                MMA(acc[0][np * 2 + 0], ah[0], bl);
                MMA(acc[0][np * 2 + 1], ah[0], bl + 2);
                MMA(acc[1][np * 2 + 0], ah[1], bl);
                MMA(acc[1][np * 2 + 1], ah[1], bl + 2);
            }
        }
        stg++; if (stg >= NSTAGE) stg -= NSTAGE;
    }

    // ---- epilogue: bias + store ----
#pragma unroll
    for (int mt = 0; mt < 2; mt++) {
#pragma unroll
        for (int nt = 0; nt < 8; nt++) {
            int col = n0 + wn * 64 + nt * 8 + (lane & 3) * 2;
            float bx = __ldg(bias + col), by = __ldg(bias + col + 1);
            int r0 = m0 + wm * 32 + mt * 16 + (lane >> 2);
            if (r0 < N_NODES) {
                float2 v = make_float2(acc[mt][nt][0] + bx, acc[mt][nt][1] + by);
                *(float2*)(out + (size_t)r0 * C + col) = v;
            }
            int r1 = r0 + 8;
            if (r1 < N_NODES) {
                float2 v = make_float2(acc[mt][nt][2] + bx, acc[mt][nt][3] + by);
                *(float2*)(out + (size_t)r1 * C + col) = v;
            }
        }
    }
}

// ---------------- launcher ----------------
extern "C" void kernel_launch(void* const* d_in, const int* in_sizes, int n_in,
                              void* d_out, int out_size) {
    const float* x    = (const float*)d_in[0];
    const int*   ei   = (const int*)d_in[1];
    const float* ew   = (const float*)d_in[2];
    const float* w    = (const float*)d_in[3];
    const float* bias = (const float*)d_in[4];
    float* out = (float*)d_out;

    cudaFuncSetAttribute(gemm_mma, cudaFuncAttributeMaxDynamicSharedMemorySize, SM_GEMM);

    int nb_nodes = (N_NODES + 255) / 256;
    int nb_edges = (N_EDGES + 255) / 256;

    init_kernel<<<nb_nodes, 256>>>(ei);
    count_kernel<<<nb_edges, 256>>>(ei);
    scan_kernel<<<1, 1024>>>();
    scatter_kernel<<<nb_edges, 256>>>(ei, ew);

    xconv_kernel<<<N_NODES / 4, 256>>>(x);
    bprep_kernel<<<NKTILE * 2, 256>>>(w);

    spmm_kernel<<<N_NODES / 4, 256>>>(x, 0, -1, 1, 1.0f,  0.0f, 1);  // T1
    spmm_kernel<<<N_NODES / 4, 256>>>(x, 1,  0, 2, 2.0f, -1.0f, 1);  // T2
    spmm_kernel<<<N_NODES / 4, 256>>>(x, 2,  1, 3, 2.0f, -1.0f, 1);  // T3
    spmm_kernel<<<N_NODES / 4, 256>>>(x, 3,  2, 4, 2.0f, -1.0f, 0);  // T4 (bf16 only)

    dim3 grid(2, (N_NODES + 127) / 128);   // x = n-block (fast), y = m-block
    gemm_mma<<<grid, 256, SM_GEMM>>>(bias, out);
}

// round 17
// speedup vs baseline: 1.1591x; 1.1591x over previous
#include <cuda_runtime.h>
#include <cuda_fp16.h>
#include <cstdint>

#define N_NODES 40000
#define N_EDGES 320000
#define C 256
#define KORD 5

#define NKTILE 40          // 5 segs x 8 k32-tiles
#define ACOLS 2560         // per-row fp16 cols: 5 segs x (256 hi + 256 lo)

// ---------------- scratch (device globals; no allocation allowed) ----------------
__device__ int   g_is64;
__device__ int   g_cnt[N_NODES];
__device__ int   g_fill[N_NODES];
__device__ int   g_rowptr[N_NODES + 1];
__device__ float g_dis[N_NODES];
__device__ int   g_col[N_EDGES];
__device__ float g_val[N_EDGES];
__device__ float g_T1[(size_t)N_NODES * C];
__device__ float g_T2[(size_t)N_NODES * C];
__device__ float g_T3[(size_t)N_NODES * C];
__device__ float g_T4[(size_t)N_NODES * C];
__device__ __align__(16) __half g_Abf[(size_t)N_NODES * ACOLS];      // ~205 MB (fp16 hi/lo)
__device__ __align__(16) __half g_Bw[(size_t)NKTILE * 32 * 256];     // fp16 weight tiles

__device__ __forceinline__ float* selT(int i) {
    switch (i) {
        case 1: return g_T1;
        case 2: return g_T2;
        case 3: return g_T3;
        default: return g_T4;
    }
}
__device__ __forceinline__ int edge_idx(const int* __restrict__ ei32, int which, int e) {
    if (g_is64) {
        const long long* p = (const long long*)ei32;
        return (int)p[(size_t)which * N_EDGES + e];
    }
    return ei32[which * N_EDGES + e];
}
__device__ __forceinline__ uint32_t smem_u32(const void* p) {
    uint32_t a;
    asm("{ .reg .u64 t; cvta.to.shared.u64 t, %1; cvt.u32.u64 %0, t; }" : "=r"(a) : "l"(p));
    return a;
}

// ---------------- setup kernels ----------------
__global__ void init_kernel(const int* __restrict__ ei32) {
    int i = blockIdx.x * blockDim.x + threadIdx.x;
    if (i < N_NODES) { g_cnt[i] = 0; g_fill[i] = 0; }
    if (blockIdx.x == 0 && threadIdx.x == 0) {
        int is64 = 1;
        for (int k = 0; k < 64; k++)
            if (ei32[2 * k + 1] != 0) { is64 = 0; break; }
        g_is64 = is64;
    }
}
__global__ void count_kernel(const int* __restrict__ ei32) {
    int e = blockIdx.x * blockDim.x + threadIdx.x;
    if (e < N_EDGES) {
        int r = edge_idx(ei32, 0, e);
        int c = edge_idx(ei32, 1, e);
        if (r != c && r >= 0 && r < N_NODES) atomicAdd(&g_cnt[r], 1);
    }
}

// single-block scan: 1024 threads x 40 items, warp-shuffle block scan + fused deg_inv_sqrt
#define SCAN_IPT 40
__global__ __launch_bounds__(1024, 1)
void scan_kernel() {
    __shared__ int wsum[32];
    int tid = threadIdx.x;
    int lane = tid & 31, wid = tid >> 5;
    int base = tid * SCAN_IPT;

    int vals[SCAN_IPT];
    int sum = 0;
#pragma unroll
    for (int i = 0; i < SCAN_IPT; i++) {
        int idx = base + i;
        int v = (idx < N_NODES) ? g_cnt[idx] : 0;
        sum += v;
        vals[i] = sum;
    }
    int s = sum;
#pragma unroll
    for (int off = 1; off < 32; off <<= 1) {
        int t = __shfl_up_sync(0xFFFFFFFFu, s, off);
        if (lane >= off) s += t;
    }
    if (lane == 31) wsum[wid] = s;
    __syncthreads();
    if (wid == 0) {
        int w = wsum[lane];
#pragma unroll
        for (int off = 1; off < 32; off <<= 1) {
            int t = __shfl_up_sync(0xFFFFFFFFu, w, off);
            if (lane >= off) w += t;
        }
        wsum[lane] = w;
    }
    __syncthreads();
    int prefix = s - sum + (wid > 0 ? wsum[wid - 1] : 0);

    if (tid == 0) g_rowptr[0] = 0;
#pragma unroll
    for (int i = 0; i < SCAN_IPT; i++) {
        int idx = base + i;
        if (idx < N_NODES) {
            g_rowptr[idx + 1] = prefix + vals[i];
            int d = (i == 0) ? vals[0] : (vals[i] - vals[i - 1]);
            g_dis[idx] = (d > 0) ? rsqrtf((float)d) : 0.0f;
        }
    }
}

__global__ void scatter_kernel(const int* __restrict__ ei32,
                               const float* __restrict__ ew) {
    int e = blockIdx.x * blockDim.x + threadIdx.x;
    if (e < N_EDGES) {
        int r = edge_idx(ei32, 0, e);
        int c = edge_idx(ei32, 1, e);
        if (r != c && r >= 0 && r < N_NODES && c >= 0 && c < N_NODES) {
            float lap = -g_dis[r] * ew[e] * g_dis[c];
            int pos = g_rowptr[r] + atomicAdd(&g_fill[r], 1);
            g_col[pos] = c;
            g_val[pos] = lap;
        }
    }
}

// pack 4 floats -> fp16 hi/lo uint2 stores
__device__ __forceinline__ void store_hilo4(__half* dst, float4 r) {
    __half h0 = __float2half(r.x), h1 = __float2half(r.y);
    __half h2 = __float2half(r.z), h3 = __float2half(r.w);
    __half l0 = __float2half(r.x - __half2float(h0));
    __half l1 = __float2half(r.y - __half2float(h1));
    __half l2 = __float2half(r.z - __half2float(h2));
    __half l3 = __float2half(r.w - __half2float(h3));
    __half2 hp0 = {h0, h1}, hp1 = {h2, h3}, lp0 = {l0, l1}, lp1 = {l2, l3};
    uint2 hv = make_uint2(*(uint32_t*)&hp0, *(uint32_t*)&hp1);
    uint2 lv = make_uint2(*(uint32_t*)&lp0, *(uint32_t*)&lp1);
    *(uint2*)dst = hv;
    *(uint2*)(dst + 256) = lv;
}

// seg-0 conversion: x -> fp16 hi/lo, float4 per thread, 4 rows/block
__global__ void xconv_kernel(const float* __restrict__ x) {
    int tid = threadIdx.x;
    int row = blockIdx.x * 4 + (tid >> 6);
    int c4 = (tid & 63) * 4;
    float4 v = *(const float4*)(x + (size_t)row * C + c4);
    store_hilo4(g_Abf + (size_t)row * ACOLS + c4, v);
}

// weight prep: g_Bw[ktile][j][n] = fp16(W[seg][kk+j][n])
__global__ void bprep_kernel(const float* __restrict__ w) {
    int ktile = blockIdx.x;               // 0..39
    int seg = ktile >> 3, kk = (ktile & 7) << 5;
    int n = threadIdx.x;
    const float* Wseg = w + (size_t)seg * C * C;
    __half* dst = g_Bw + (size_t)ktile * 32 * 256;
    for (int j = 0; j < 32; j++) {
        dst[j * 256 + n] = __float2half(Wseg[(size_t)(kk + j) * C + n]);
    }
}

// ---------------- CSR SpMM (+ fused fp16 hi/lo conversion) ----------------
// 4 rows per block, 64 threads/row, float4 per thread, 2-edge unroll (R11-proven).
__global__ void spmm_kernel(const float* __restrict__ x,
                            int vsel, int ssel, int dsel,
                            float alpha, float beta, int store_f32) {
    const float* v   = (vsel == 0) ? x : selT(vsel);
    const float* sub = (ssel < 0) ? nullptr : ((ssel == 0) ? x : selT(ssel));
    float* out = selT(dsel);

    int tid = threadIdx.x;
    int row = blockIdx.x * 4 + (tid >> 6);
    int c4 = (tid & 63) * 4;

    int s = g_rowptr[row], e = g_rowptr[row + 1];
    float4 a0 = make_float4(0.f, 0.f, 0.f, 0.f);
    float4 a1 = make_float4(0.f, 0.f, 0.f, 0.f);
    int j = s;
    for (; j + 2 <= e; j += 2) {
        int  c0 = g_col[j],   c1 = g_col[j + 1];
        float w0 = g_val[j],  w1 = g_val[j + 1];
        float4 v0 = *(const float4*)(v + (size_t)c0 * C + c4);
        float4 v1 = *(const float4*)(v + (size_t)c1 * C + c4);
        a0.x += w0 * v0.x; a0.y += w0 * v0.y; a0.z += w0 * v0.z; a0.w += w0 * v0.w;
        a1.x += w1 * v1.x; a1.y += w1 * v1.y; a1.z += w1 * v1.z; a1.w += w1 * v1.w;
    }
    if (j < e) {
        int c0 = g_col[j];
        float w0 = g_val[j];
        float4 v0 = *(const float4*)(v + (size_t)c0 * C + c4);
        a0.x += w0 * v0.x; a0.y += w0 * v0.y; a0.z += w0 * v0.z; a0.w += w0 * v0.w;
    }
    float4 r;
    r.x = alpha * (a0.x + a1.x);
    r.y = alpha * (a0.y + a1.y);
    r.z = alpha * (a0.z + a1.z);
    r.w = alpha * (a0.w + a1.w);
    if (sub) {
        float4 sv = *(const float4*)(sub + (size_t)row * C + c4);
        r.x += beta * sv.x; r.y += beta * sv.y; r.z += beta * sv.z; r.w += beta * sv.w;
    }
    if (store_f32) *(float4*)(out + (size_t)row * C + c4) = r;
    store_hilo4(g_Abf + (size_t)row * ACOLS + dsel * 512 + c4, r);
}

// ---------------- fp16 mma.sync GEMM, 2-term split, 3-stage cp.async ----------------
// out = sum over 40 k32-tiles of (Ahi + Alo) @ Wfp16 + bias
// CTA tile 128x128, 256 threads (8 warps: 4M x 2N), grid (2, 313), 2 CTAs/SM.
#define MMA(c, a, b) \
    asm volatile("mma.sync.aligned.m16n8k16.row.col.f32.f16.f16.f32 " \
        "{%0,%1,%2,%3}, {%4,%5,%6,%7}, {%8,%9}, {%0,%1,%2,%3};" \
        : "+f"((c)[0]), "+f"((c)[1]), "+f"((c)[2]), "+f"((c)[3]) \
        : "r"((a)[0]), "r"((a)[1]), "r"((a)[2]), "r"((a)[3]), "r"((b)[0]), "r"((b)[1]))

#define LDM_X4(r, a) \
    asm volatile("ldmatrix.sync.aligned.m8n8.x4.shared.b16 {%0,%1,%2,%3}, [%4];" \
        : "=r"((r)[0]), "=r"((r)[1]), "=r"((r)[2]), "=r"((r)[3]) : "r"(a))

#define LDM_X4T(r, a) \
    asm volatile("ldmatrix.sync.aligned.m8n8.x4.trans.shared.b16 {%0,%1,%2,%3}, [%4];" \
        : "=r"((r)[0]), "=r"((r)[1]), "=r"((r)[2]), "=r"((r)[3]) : "r"(a))

#define CP16(d, s, n) \
    asm volatile("cp.async.cg.shared.global [%0], [%1], 16, %2;" \
        :: "r"(d), "l"(s), "r"(n) : "memory")
#define CP_COMMIT() asm volatile("cp.async.commit_group;" ::: "memory")
#define CP_WAIT(n)  asm volatile("cp.async.wait_group %0;" :: "n"(n) : "memory")

// stage: Ahi 8KB @0, Alo 8KB @8192, W 8KB @16384
#define STG_BYTES 24576
#define NSTAGE 3
#define SM_GEMM (NSTAGE * STG_BYTES)

__global__ __launch_bounds__(256, 2)
void gemm_mma(const float* __restrict__ bias, float* __restrict__ out) {
    extern __shared__ char smem[];
    uint32_t sb = smem_u32(smem);

    int tid = threadIdx.x;
    int lane = tid & 31;
    int wid = tid >> 5;
    int wm = wid & 3, wn = wid >> 2;     // 4 M-warps x 2 N-warps
    int m0 = blockIdx.y * 128;
    int n0 = blockIdx.x * 128;

    // A staging: 512 granules/half (128 rows x 4 chunks of 16B), 2 per thread per half
    int aG0 = tid * 2, aG1 = tid * 2 + 1;
    int aR0 = aG0 >> 2, aC0 = aG0 & 3;
    int aR1 = aG1 >> 2, aC1 = aG1 & 3;
    uint32_t aSz0 = (m0 + aR0 < N_NODES) ? 16u : 0u;
    uint32_t aSz1 = (m0 + aR1 < N_NODES) ? 16u : 0u;
    uint32_t aDst0 = aR0 * 64 + ((aC0 ^ ((aR0 >> 1) & 3)) << 4);
    uint32_t aDst1 = aR1 * 64 + ((aC1 ^ ((aR1 >> 1) & 3)) << 4);
    // B staging: 512 granules (32 rows x 16 chunks), 2 per thread
    int bG0 = tid * 2, bG1 = tid * 2 + 1;
    int bR0 = bG0 >> 4, bC0 = bG0 & 15;
    int bR1 = bG1 >> 4, bC1 = bG1 & 15;
    uint32_t bDst0 = bR0 * 256 + ((bC0 ^ (bR0 & 7)) << 4);
    uint32_t bDst1 = bR1 * 256 + ((bC1 ^ (bR1 & 7)) << 4);

    // ldmatrix offsets — A rows 64B (4 chunks), B rows 256B (16 chunks)
    uint32_t aOff[2][2];
#pragma unroll
    for (int mt = 0; mt < 2; mt++)
#pragma unroll
        for (int ks = 0; ks < 2; ks++) {
            int row = wm * 32 + mt * 16 + (lane & 15);
            int ch = ks * 2 + (lane >> 4);
            aOff[mt][ks] = row * 64 + ((ch ^ ((row >> 1) & 3)) << 4);
        }
    uint32_t bOff[4][2];
#pragma unroll
    for (int np = 0; np < 4; np++)
#pragma unroll
        for (int ks = 0; ks < 2; ks++) {
            int row = ks * 16 + ((lane >> 3) & 1) * 8 + (lane & 7);
            int ch = wn * 8 + np * 2 + (lane >> 4);
            bOff[np][ks] = row * 256 + ((ch ^ (row & 7)) << 4);
        }

    float acc[2][8][4];
#pragma unroll
    for (int i = 0; i < 2; i++)
#pragma unroll
        for (int j = 0; j < 8; j++)
#pragma unroll
            for (int q = 0; q < 4; q++) acc[i][j][q] = 0.f;

    auto issue = [&](int ktile, int stg) {
        uint32_t base = sb + stg * STG_BYTES;
        int seg = ktile >> 3, kk = (ktile & 7) << 5;
        const __half* a0 =
            g_Abf + (size_t)(m0 + aR0) * ACOLS + seg * 512 + kk + aC0 * 8;
        const __half* a1 =
            g_Abf + (size_t)(m0 + aR1) * ACOLS + seg * 512 + kk + aC1 * 8;
        CP16(base + aDst0, a0, aSz0);                 // Ahi
        CP16(base + aDst1, a1, aSz1);
        CP16(base + 8192 + aDst0, a0 + 256, aSz0);    // Alo
        CP16(base + 8192 + aDst1, a1 + 256, aSz1);
        const __half* bw = g_Bw + (size_t)ktile * 32 * 256 + n0;
        CP16(base + 16384 + bDst0, bw + bR0 * 256 + bC0 * 8, 16u);  // W
        CP16(base + 16384 + bDst1, bw + bR1 * 256 + bC1 * 8, 16u);
    };

    issue(0, 0); CP_COMMIT();
    issue(1, 1); CP_COMMIT();

    int stg = 0;
    for (int kt = 0; kt < NKTILE; kt++) {
        if (kt < NKTILE - 1) { CP_WAIT(1); } else { CP_WAIT(0); }
        __syncthreads();
        if (kt + 2 < NKTILE) {
            int ns = stg + 2; if (ns >= NSTAGE) ns -= NSTAGE;
            issue(kt + 2, ns);
            CP_COMMIT();
        }

        uint32_t S = sb + stg * STG_BYTES;
        uint32_t Ahi = S, Alo = S + 8192, Wb = S + 16384;
#pragma unroll
        for (int ks = 0; ks < 2; ks++) {
            uint32_t ah[2][4], al[2][4];
            LDM_X4(ah[0], Ahi + aOff[0][ks]);
            LDM_X4(ah[1], Ahi + aOff[1][ks]);
            LDM_X4(al[0], Alo + aOff[0][ks]);
            LDM_X4(al[1], Alo + aOff[1][ks]);
#pragma unroll
            for (int np = 0; np < 4; np++) {
                uint32_t bw[4];
                LDM_X4T(bw, Wb + bOff[np][ks]);
                MMA(acc[0][np * 2 + 0], ah[0], bw);
                MMA(acc[0][np * 2 + 1], ah[0], bw + 2);
                MMA(acc[1][np * 2 + 0], ah[1], bw);
                MMA(acc[1][np * 2 + 1], ah[1], bw + 2);
                MMA(acc[0][np * 2 + 0], al[0], bw);
                MMA(acc[0][np * 2 + 1], al[0], bw + 2);
                MMA(acc[1][np * 2 + 0], al[1], bw);
                MMA(acc[1][np * 2 + 1], al[1], bw + 2);
            }
        }
        stg++; if (stg >= NSTAGE) stg -= NSTAGE;
    }

    // ---- epilogue: bias + store ----
#pragma unroll
    for (int mt = 0; mt < 2; mt++) {
#pragma unroll
        for (int nt = 0; nt < 8; nt++) {
            int col = n0 + wn * 64 + nt * 8 + (lane & 3) * 2;
            float bx = __ldg(bias + col), by = __ldg(bias + col + 1);
            int r0 = m0 + wm * 32 + mt * 16 + (lane >> 2);
            if (r0 < N_NODES) {
                float2 v = make_float2(acc[mt][nt][0] + bx, acc[mt][nt][1] + by);
                *(float2*)(out + (size_t)r0 * C + col) = v;
            }
            int r1 = r0 + 8;
            if (r1 < N_NODES) {
                float2 v = make_float2(acc[mt][nt][2] + bx, acc[mt][nt][3] + by);
                *(float2*)(out + (size_t)r1 * C + col) = v;
            }
        }
    }
}

// ---------------- launcher ----------------
extern "C" void kernel_launch(void* const* d_in, const int* in_sizes, int n_in,
                              void* d_out, int out_size) {
    const float* x    = (const float*)d_in[0];
    const int*   ei   = (const int*)d_in[1];
    const float* ew   = (const float*)d_in[2];
    const float* w    = (const float*)d_in[3];
    const float* bias = (const float*)d_in[4];
    float* out = (float*)d_out;

    cudaFuncSetAttribute(gemm_mma, cudaFuncAttributeMaxDynamicSharedMemorySize, SM_GEMM);

    int nb_nodes = (N_NODES + 255) / 256;
    int nb_edges = (N_EDGES + 255) / 256;

    init_kernel<<<nb_nodes, 256>>>(ei);
    count_kernel<<<nb_edges, 256>>>(ei);
    scan_kernel<<<1, 1024>>>();
    scatter_kernel<<<nb_edges, 256>>>(ei, ew);

    xconv_kernel<<<N_NODES / 4, 256>>>(x);
    bprep_kernel<<<NKTILE, 256>>>(w);

    spmm_kernel<<<N_NODES / 4, 256>>>(x, 0, -1, 1, 1.0f,  0.0f, 1);  // T1
    spmm_kernel<<<N_NODES / 4, 256>>>(x, 1,  0, 2, 2.0f, -1.0f, 1);  // T2
    spmm_kernel<<<N_NODES / 4, 256>>>(x, 2,  1, 3, 2.0f, -1.0f, 1);  // T3
    spmm_kernel<<<N_NODES / 4, 256>>>(x, 3,  2, 4, 2.0f, -1.0f, 0);  // T4 (fp16 only)

    dim3 grid(2, (N_NODES + 127) / 128);   // x = n-block (fast), y = m-block
    gemm_mma<<<grid, 256, SM_GEMM>>>(bias, out);
}